// round 1
// baseline (speedup 1.0000x reference)
#include <cuda_runtime.h>
#include <cstdint>

// Problem constants (shapes fixed by the dataset)
#define SQ 50          // qubits
#define SP 3           // pauli basis
#define SS 64          // heads
#define TILE 256       // words per block
#define TROW 151       // padded row stride (151 mod 32 = 23, coprime with 32 -> conflict-free)

// Packed heads layout: [q][j=s/2][8] = {h0s0,h0s1, h1s0,h1s1, h2s0,h2s1, 0,0}
#define HQ_FLOATS 256          // 32 pairs * 8 floats per q
#define H_TOTAL (SQ * HQ_FLOATS)   // 12800 floats

__device__ double g_accum;
__device__ float  g_heads[H_TOTAL];
__device__ float  g_hr[SS];

__device__ __forceinline__ float softplus20(float x) {
    float y = x * 20.0f;
    // jax.nn.softplus: max(x,0) + log1p(exp(-|x|))
    return fmaxf(y, 0.0f) + log1pf(expf(-fabsf(y)));
}

// ---------------------------------------------------------------------------
// Prep: normalize heads + head ratios, zero the accumulator.
// ---------------------------------------------------------------------------
__global__ void prep_kernel(const float* __restrict__ heads_param,
                            const float* __restrict__ hr_param) {
    __shared__ float s_hr[SS];
    __shared__ float s_sum;
    int tid = threadIdx.x;

    if (tid == 0) g_accum = 0.0;

    if (tid < SS) s_hr[tid] = softplus20(hr_param[tid]);
    __syncthreads();
    if (tid == 0) {
        float s = 0.0f;
        for (int i = 0; i < SS; i++) s += s_hr[i];
        s_sum = fmaxf(s, 1e-12f);
    }
    __syncthreads();
    if (tid < SS) {
        g_hr[tid] = (s_hr[tid] / s_sum + 0.001f / (float)SS) / 1.001f;
    }

    // 3200 (s,q) pairs
    for (int i = tid; i < SS * SQ; i += blockDim.x) {
        int s = i / SQ;
        int q = i - s * SQ;
        const float* hp = heads_param + (s * SQ + q) * SP;
        float h0 = softplus20(hp[0]);
        float h1 = softplus20(hp[1]);
        float h2 = softplus20(hp[2]);
        float inv = 1.0f / fmaxf(h0 + h1 + h2, 1e-12f);
        h0 *= inv; h1 *= inv; h2 *= inv;
        int j = s >> 1, o = s & 1;
        float* dst = g_heads + q * HQ_FLOATS + j * 8;
        dst[0 + o] = h0;
        dst[2 + o] = h1;
        dst[4 + o] = h2;
        dst[6 + o] = 0.0f;   // pad
    }
}

// ---------------------------------------------------------------------------
// Main: per-thread one pauli word, 32 packed f32x2 accumulators over 64 heads.
// ---------------------------------------------------------------------------
__global__ void __launch_bounds__(TILE, 1)
main_kernel(const float* __restrict__ pauli,
            const float* __restrict__ coeff,
            int N) {
    extern __shared__ float smem[];
    float* sh_h  = smem;                         // 12800 floats (51200 B), 16B aligned
    float* sh_hr = smem + H_TOTAL;               // 64 floats
    float* sh_t  = smem + H_TOTAL + SS;          // 256*151 floats, offset 51456 B (16B aligned)

    const int tid = threadIdx.x;

    // Stage packed heads (vectorized broadcast-friendly copy)
    {
        const float4* src = (const float4*)g_heads;
        float4*       dst = (float4*)sh_h;
        #pragma unroll 4
        for (int i = tid; i < H_TOTAL / 4; i += TILE) dst[i] = src[i];
    }
    if (tid < SS) sh_hr[tid] = g_hr[tid];

    // Stage pauli tile: coalesced global reads, padded-row scatter to smem
    const int base  = blockIdx.x * TILE;
    const int valid = min(TILE, N - base);
    const int total = valid * (SQ * SP);
    const float* gsrc = pauli + (size_t)base * (SQ * SP);
    for (int f = tid; f < total; f += TILE) {
        int row = f / (SQ * SP);
        int col = f - row * (SQ * SP);
        sh_t[row * TROW + col] = gsrc[f];
    }
    __syncthreads();

    // 32 packed pairs of per-head running products, init to (1.0f, 1.0f)
    uint64_t acc[32];
    #pragma unroll
    for (int j = 0; j < 32; j++) acc[j] = 0x3F8000003F800000ull;

    const float* trow = sh_t + tid * TROW;

    #pragma unroll 1
    for (int q = 0; q < SQ; q++) {
        float t0 = trow[q * 3 + 0];
        float t1 = trow[q * 3 + 1];
        float t2 = trow[q * 3 + 2];
        uint64_t T0, T1, T2;
        asm("mov.b64 %0, {%1, %2};" : "=l"(T0) : "f"(t0), "f"(t0));
        asm("mov.b64 %0, {%1, %2};" : "=l"(T1) : "f"(t1), "f"(t1));
        asm("mov.b64 %0, {%1, %2};" : "=l"(T2) : "f"(t2), "f"(t2));

        const ulonglong2* hq = (const ulonglong2*)(sh_h + q * HQ_FLOATS);
        #pragma unroll
        for (int j = 0; j < 32; j++) {
            ulonglong2 hA = hq[2 * j];       // {(h0s0,h0s1), (h1s0,h1s1)}
            ulonglong2 hB = hq[2 * j + 1];   // {(h2s0,h2s1), pad}
            uint64_t d;
            asm("mul.rn.f32x2 %0, %1, %2;"     : "=l"(d) : "l"(T2), "l"(hB.x));
            asm("fma.rn.f32x2 %0, %1, %2, %3;" : "=l"(d) : "l"(T1), "l"(hA.y), "l"(d));
            asm("fma.rn.f32x2 %0, %1, %2, %3;" : "=l"(d) : "l"(T0), "l"(hA.x), "l"(d));
            asm("mul.rn.f32x2 %0, %1, %2;"     : "=l"(acc[j]) : "l"(acc[j]), "l"(d));
        }
    }

    // cov[n] = sum_s hr[s] * prod_q
    float cov = 0.0f;
    #pragma unroll
    for (int j = 0; j < 32; j++) {
        float lo, hi;
        asm("mov.b64 {%0, %1}, %2;" : "=f"(lo), "=f"(hi) : "l"(acc[j]));
        cov = fmaf(sh_hr[2 * j],     lo, cov);
        cov = fmaf(sh_hr[2 * j + 1], hi, cov);
    }

    double v = 0.0;
    const int n = base + tid;
    if (n < N) {
        float c = coeff[n];
        v = (double)((c * c) / cov);
    }

    // block reduction in double
    #pragma unroll
    for (int off = 16; off; off >>= 1)
        v += __shfl_down_sync(0xFFFFFFFFu, v, off);

    __syncthreads();                  // done reading sh_t; reuse as scratch
    double* red = (double*)sh_t;
    if ((tid & 31) == 0) red[tid >> 5] = v;
    __syncthreads();
    if (tid == 0) {
        double s = 0.0;
        #pragma unroll
        for (int w = 0; w < TILE / 32; w++) s += red[w];
        atomicAdd(&g_accum, s);
    }
}

__global__ void finish_kernel(float* out) {
    out[0] = (float)g_accum;
}

// ---------------------------------------------------------------------------
extern "C" void kernel_launch(void* const* d_in, const int* in_sizes, int n_in,
                              void* d_out, int out_size) {
    const float* pauli = (const float*)d_in[0];   // [N, 50, 3] f32
    const float* coeff = (const float*)d_in[1];   // [N] f32
    const float* heads = (const float*)d_in[2];   // [64, 50, 3] f32
    const float* hr    = (const float*)d_in[3];   // [64] f32
    const int N = in_sizes[1];

    const size_t smem = (size_t)(H_TOTAL + SS + TILE * TROW) * sizeof(float); // 206080 B
    cudaFuncSetAttribute(main_kernel, cudaFuncAttributeMaxDynamicSharedMemorySize, (int)smem);

    prep_kernel<<<1, 256>>>(heads, hr);
    const int grid = (N + TILE - 1) / TILE;
    main_kernel<<<grid, TILE, smem>>>(pauli, coeff, N);
    finish_kernel<<<1, 1>>>((float*)d_out);
}

// round 3
// speedup vs baseline: 1.0888x; 1.0888x over previous
#include <cuda_runtime.h>
#include <cstdint>

// Problem constants (shapes fixed by the dataset)
#define SQ 50          // qubits
#define SP 3           // pauli basis
#define SS 64          // heads
#define TILE 256       // words per block
#define TROW 151       // padded row stride (151 mod 32 = 23 -> conflict-free)

// Packed heads layout: [q][j=s/2][8] = {h0s0,h0s1, h1s0,h1s1, h2s0,h2s1, 0,0}
#define HQ_FLOATS 256
#define H_TOTAL (SQ * HQ_FLOATS)   // 12800 floats = 51.2 KB

__device__ double       g_accum;
__device__ unsigned int g_count;
__device__ float        g_heads[H_TOTAL];
__device__ float        g_hr[SS];

__device__ __forceinline__ float softplus20(float x) {
    float y = x * 20.0f;
    return fmaxf(y, 0.0f) + log1pf(expf(-fabsf(y)));
}

// ---------------------------------------------------------------------------
// Prep: normalize heads + head ratios. Parallel across blocks.
// ---------------------------------------------------------------------------
__global__ void prep_kernel(const float* __restrict__ heads_param,
                            const float* __restrict__ hr_param) {
    const int tid = threadIdx.x;

    if (blockIdx.x == 0 && tid == 0) { g_accum = 0.0; g_count = 0u; }

    __shared__ float s_hr[SS];
    if (tid < SS) s_hr[tid] = softplus20(hr_param[tid]);
    __syncthreads();
    if (blockIdx.x == 0 && tid < SS) {
        float s = 0.0f;
        #pragma unroll
        for (int i = 0; i < SS; i++) s += s_hr[i];
        s = fmaxf(s, 1e-12f);
        g_hr[tid] = (s_hr[tid] / s + 0.001f / (float)SS) / 1.001f;
    }

    const int stride = blockDim.x * gridDim.x;
    for (int i = blockIdx.x * blockDim.x + tid; i < SS * SQ; i += stride) {
        int s = i / SQ;
        int q = i - s * SQ;
        const float* hp = heads_param + (s * SQ + q) * SP;
        float h0 = softplus20(hp[0]);
        float h1 = softplus20(hp[1]);
        float h2 = softplus20(hp[2]);
        float inv = 1.0f / fmaxf(h0 + h1 + h2, 1e-12f);
        h0 *= inv; h1 *= inv; h2 *= inv;
        int j = s >> 1, o = s & 1;
        float* dst = g_heads + q * HQ_FLOATS + j * 8;
        dst[0 + o] = h0;
        dst[2 + o] = h1;
        dst[4 + o] = h2;
        dst[6 + o] = 0.0f;  // pad
    }
}

// ---------------------------------------------------------------------------
// Main: dot = t2c * (h2 + h0*(t0/t2c) + h1*(t1/t2c)); all-nonneg inner sums.
// cov[n] = (prod_q t2c) * sum_s hr[s] * prod_q inner[n,s,q]
// ---------------------------------------------------------------------------
__global__ void __launch_bounds__(TILE, 1)
main_kernel(const float* __restrict__ pauli,
            const float* __restrict__ coeff,
            float* __restrict__ out,
            int N, int nblocks) {
    extern __shared__ float smem[];
    float* sh_h  = smem;                         // 12800 floats
    float* sh_hr = smem + H_TOTAL;               // 64 floats
    float* sh_t  = smem + H_TOTAL + SS;          // 256*151 floats

    const int tid = threadIdx.x;

    // Stage packed heads
    {
        const float4* src = (const float4*)g_heads;
        float4*       dst = (float4*)sh_h;
        #pragma unroll
        for (int i = tid; i < H_TOTAL / 4; i += TILE) dst[i] = src[i];
    }
    if (tid < SS) sh_hr[tid] = g_hr[tid];

    // Stage pauli tile: coalesced global reads, padded-row scatter to smem
    const int base  = blockIdx.x * TILE;
    const int valid = min(TILE, N - base);
    const int total = valid * (SQ * SP);
    const float* gsrc = pauli + (size_t)base * (SQ * SP);
    for (int f = tid; f < total; f += TILE) {
        int row = f / (SQ * SP);
        int col = f - row * (SQ * SP);
        sh_t[row * TROW + col] = gsrc[f];
    }
    __syncthreads();

    // 32 packed pairs of per-head running inner-products, init to (1,1)
    uint64_t acc[32];
    #pragma unroll
    for (int j = 0; j < 32; j++) acc[j] = 0x3F8000003F800000ull;

    float p2a = 1.0f, p2b = 1.0f;   // prod of t2c, two halves
    const float* trow = sh_t + tid * TROW;

    #pragma unroll 1
    for (int q = 0; q < SQ; q++) {
        float t0 = trow[q * 3 + 0];
        float t1 = trow[q * 3 + 1];
        float t2 = trow[q * 3 + 2];
        float t2c = fmaxf(t2, 1e-12f);
        float rcp;
        asm("rcp.approx.f32 %0, %1;" : "=f"(rcp) : "f"(t2c));
        float r0 = t0 * rcp;
        float r1 = t1 * rcp;
        if (q < SQ / 2) p2a *= t2c; else p2b *= t2c;

        uint64_t R0, R1;
        asm("mov.b64 %0, {%1, %2};" : "=l"(R0) : "f"(r0), "f"(r0));
        asm("mov.b64 %0, {%1, %2};" : "=l"(R1) : "f"(r1), "f"(r1));

        const ulonglong2* hq = (const ulonglong2*)(sh_h + q * HQ_FLOATS);
        #pragma unroll
        for (int j = 0; j < 32; j++) {
            ulonglong2 Ha = hq[2 * j];        // {(h0 s0,s1), (h1 s0,s1)}
            uint64_t   Hc = hq[2 * j + 1].x;  // (h2 s0,s1)
            uint64_t d;
            asm("fma.rn.f32x2 %0, %1, %2, %3;" : "=l"(d) : "l"(Ha.x), "l"(R0), "l"(Hc));
            asm("fma.rn.f32x2 %0, %1, %2, %3;" : "=l"(d) : "l"(Ha.y), "l"(R1), "l"(d));
            asm("mul.rn.f32x2 %0, %1, %2;"     : "=l"(acc[j]) : "l"(acc[j]), "l"(d));
        }
    }

    // inner covariance sum over heads
    float cov = 0.0f;
    #pragma unroll
    for (int j = 0; j < 32; j++) {
        float lo, hi;
        asm("mov.b64 {%0, %1}, %2;" : "=f"(lo), "=f"(hi) : "l"(acc[j]));
        cov = fmaf(sh_hr[2 * j],     lo, cov);
        cov = fmaf(sh_hr[2 * j + 1], hi, cov);
    }

    double v = 0.0;
    const int n = base + tid;
    if (n < N) {
        float c = coeff[n];
        double covd = (double)cov * (double)p2a * (double)p2b;
        v = (double)(c * c) / covd;
    }

    // block reduction in double
    #pragma unroll
    for (int off = 16; off; off >>= 1)
        v += __shfl_down_sync(0xFFFFFFFFu, v, off);

    __syncthreads();                  // done reading sh_t; reuse as scratch
    double* red = (double*)sh_t;
    if ((tid & 31) == 0) red[tid >> 5] = v;
    __syncthreads();
    if (tid == 0) {
        double s = 0.0;
        #pragma unroll
        for (int w = 0; w < TILE / 32; w++) s += red[w];
        atomicAdd(&g_accum, s);
        __threadfence();
        unsigned int ticket = atomicAdd(&g_count, 1u);
        if (ticket == (unsigned int)(nblocks - 1)) {
            out[0] = (float)g_accum;
        }
    }
}

// ---------------------------------------------------------------------------
extern "C" void kernel_launch(void* const* d_in, const int* in_sizes, int n_in,
                              void* d_out, int out_size) {
    const float* pauli = (const float*)d_in[0];   // [N, 50, 3] f32
    const float* coeff = (const float*)d_in[1];   // [N] f32
    const float* heads = (const float*)d_in[2];   // [64, 50, 3] f32
    const float* hr    = (const float*)d_in[3];   // [64] f32
    const int N = in_sizes[1];

    const size_t smem = (size_t)(H_TOTAL + SS + TILE * TROW) * sizeof(float); // 206080 B
    cudaFuncSetAttribute(main_kernel, cudaFuncAttributeMaxDynamicSharedMemorySize, (int)smem);

    prep_kernel<<<25, 128>>>(heads, hr);
    const int grid = (N + TILE - 1) / TILE;
    main_kernel<<<grid, TILE, smem>>>(pauli, coeff, (float*)d_out, N, grid);
}

// round 4
// speedup vs baseline: 1.0940x; 1.0048x over previous
#include <cuda_runtime.h>
#include <cstdint>

// Problem constants (shapes fixed by the dataset)
#define SQ 50          // qubits
#define SP 3           // pauli basis
#define SS 64          // heads
#define WORDS 256      // pauli words per block
#define THREADS 512    // 16 warps: warp pairs split the 64 heads
#define TROW 156       // padded row stride in floats (624 B; 624/16=39 odd -> LDS.128 clean)

// Packed heads layout: [q][j=s/2][8] = {h0s0,h0s1, h1s0,h1s1, h2s0,h2s1, 0,0}
#define HQ_FLOATS 256
#define H_TOTAL (SQ * HQ_FLOATS)   // 12800 floats = 51.2 KB

__device__ double       g_accum;
__device__ unsigned int g_count;
__device__ float        g_heads[H_TOTAL];
__device__ float        g_hr[SS];

__device__ __forceinline__ float softplus20(float x) {
    float y = x * 20.0f;
    return fmaxf(y, 0.0f) + log1pf(expf(-fabsf(y)));
}

// ---------------------------------------------------------------------------
// Prep: normalize heads + head ratios. Parallel across blocks.
// ---------------------------------------------------------------------------
__global__ void prep_kernel(const float* __restrict__ heads_param,
                            const float* __restrict__ hr_param) {
    const int tid = threadIdx.x;

    if (blockIdx.x == 0 && tid == 0) { g_accum = 0.0; g_count = 0u; }

    __shared__ float s_hr[SS];
    if (tid < SS) s_hr[tid] = softplus20(hr_param[tid]);
    __syncthreads();
    if (blockIdx.x == 0 && tid < SS) {
        float s = 0.0f;
        #pragma unroll
        for (int i = 0; i < SS; i++) s += s_hr[i];
        s = fmaxf(s, 1e-12f);
        g_hr[tid] = (s_hr[tid] / s + 0.001f / (float)SS) / 1.001f;
    }

    const int stride = blockDim.x * gridDim.x;
    for (int i = blockIdx.x * blockDim.x + tid; i < SS * SQ; i += stride) {
        int s = i / SQ;
        int q = i - s * SQ;
        const float* hp = heads_param + (s * SQ + q) * SP;
        float h0 = softplus20(hp[0]);
        float h1 = softplus20(hp[1]);
        float h2 = softplus20(hp[2]);
        float inv = 1.0f / fmaxf(h0 + h1 + h2, 1e-12f);
        h0 *= inv; h1 *= inv; h2 *= inv;
        int j = s >> 1, o = s & 1;
        float* dst = g_heads + q * HQ_FLOATS + j * 8;
        dst[0 + o] = h0;
        dst[2 + o] = h1;
        dst[4 + o] = h2;
        dst[6 + o] = 0.0f;  // pad
    }
}

// ---------------------------------------------------------------------------
// Per-q step: dot = t2c * (h2 + h0*(t0/t2c) + h1*(t1/t2c)); 16 head pairs.
// ---------------------------------------------------------------------------
__device__ __forceinline__ void proc_q(
    int qi, float t0, float t1, float t2,
    const float* __restrict__ sh_hhalf,   // sh_h + half*128
    uint64_t* __restrict__ acc,
    float& p2a, float& p2b)
{
    float t2c = fmaxf(t2, 1e-12f);
    float rcp;
    asm("rcp.approx.f32 %0, %1;" : "=f"(rcp) : "f"(t2c));
    float r0 = t0 * rcp;
    float r1 = t1 * rcp;
    if (qi < SQ / 2) p2a *= t2c; else p2b *= t2c;

    uint64_t R0, R1;
    asm("mov.b64 %0, {%1, %2};" : "=l"(R0) : "f"(r0), "f"(r0));
    asm("mov.b64 %0, {%1, %2};" : "=l"(R1) : "f"(r1), "f"(r1));

    const ulonglong2* hq = (const ulonglong2*)(sh_hhalf + qi * HQ_FLOATS);
    #pragma unroll
    for (int j = 0; j < 16; j++) {
        ulonglong2 Ha = hq[2 * j];        // {(h0 s0,s1), (h1 s0,s1)}
        uint64_t   Hc = hq[2 * j + 1].x;  // (h2 s0,s1)
        uint64_t d;
        asm("fma.rn.f32x2 %0, %1, %2, %3;" : "=l"(d) : "l"(Ha.x), "l"(R0), "l"(Hc));
        asm("fma.rn.f32x2 %0, %1, %2, %3;" : "=l"(d) : "l"(Ha.y), "l"(R1), "l"(d));
        asm("mul.rn.f32x2 %0, %1, %2;"     : "=l"(acc[j]) : "l"(acc[j]), "l"(d));
    }
}

// ---------------------------------------------------------------------------
// Main: warp 2k = heads 0-31, warp 2k+1 = heads 32-63, same 32 words.
// ---------------------------------------------------------------------------
__global__ void __launch_bounds__(THREADS, 1)
main_kernel(const float* __restrict__ pauli,
            const float* __restrict__ coeff,
            float* __restrict__ out,
            int N, int nblocks) {
    extern __shared__ float smem[];
    float*  sh_h       = smem;                       // 12800 floats
    float*  sh_hr      = smem + H_TOTAL;             // 64
    float*  sh_partial = smem + H_TOTAL + SS;        // 256 (half-1 partials)
    double* sh_red     = (double*)(smem + H_TOTAL + SS + WORDS);  // 8 doubles
    float*  sh_t       = smem + H_TOTAL + SS + WORDS + 16;        // 256*156, 16B aligned

    const int tid  = threadIdx.x;
    const int wid  = tid >> 5;
    const int lane = tid & 31;

    // Stage packed heads
    {
        const float4* src = (const float4*)g_heads;
        float4*       dst = (float4*)sh_h;
        #pragma unroll
        for (int i = tid; i < H_TOTAL / 4; i += THREADS) dst[i] = src[i];
    }
    if (tid < SS) sh_hr[tid] = g_hr[tid];

    // Stage pauli tile: coalesced global reads, padded-row scatter
    const int base  = blockIdx.x * WORDS;
    const int valid = min(WORDS, N - base);
    const int total = valid * (SQ * SP);
    const float* gsrc = pauli + (size_t)base * (SQ * SP);
    for (int f = tid; f < total; f += THREADS) {
        int row = f / (SQ * SP);
        int col = f - row * (SQ * SP);
        sh_t[row * TROW + col] = gsrc[f];
    }
    __syncthreads();

    const int half      = wid & 1;
    const int wordlocal = ((wid >> 1) << 5) + lane;   // 0..255
    const float* trow   = sh_t + wordlocal * TROW;
    const float* sh_hhalf = sh_h + half * 128;        // 16 pairs * 8 floats

    uint64_t acc[16];
    #pragma unroll
    for (int j = 0; j < 16; j++) acc[j] = 0x3F8000003F800000ull;
    float p2a = 1.0f, p2b = 1.0f;

    // 48 q in 12 chunks of 4 via 3x LDS.128 each
    const float4* tv = (const float4*)trow;
    #pragma unroll
    for (int c = 0; c < 12; c++) {
        float4 A = tv[3 * c + 0];
        float4 B = tv[3 * c + 1];
        float4 C = tv[3 * c + 2];
        proc_q(4 * c + 0, A.x, A.y, A.z, sh_hhalf, acc, p2a, p2b);
        proc_q(4 * c + 1, A.w, B.x, B.y, sh_hhalf, acc, p2a, p2b);
        proc_q(4 * c + 2, B.z, B.w, C.x, sh_hhalf, acc, p2a, p2b);
        proc_q(4 * c + 3, C.y, C.z, C.w, sh_hhalf, acc, p2a, p2b);
    }
    // q = 48, 49 (cols 144..149, 8B-aligned)
    {
        const float2* t2v = (const float2*)(trow + 144);
        float2 u = t2v[0], v2 = t2v[1], w2 = t2v[2];
        proc_q(48, u.x,  u.y,  v2.x, sh_hhalf, acc, p2a, p2b);
        proc_q(49, v2.y, w2.x, w2.y, sh_hhalf, acc, p2a, p2b);
    }

    // hr-weighted sum over this half's 32 heads
    float part = 0.0f;
    const float* hrh = sh_hr + half * 32;
    #pragma unroll
    for (int j = 0; j < 16; j++) {
        float lo, hi;
        asm("mov.b64 {%0, %1}, %2;" : "=f"(lo), "=f"(hi) : "l"(acc[j]));
        part = fmaf(hrh[2 * j],     lo, part);
        part = fmaf(hrh[2 * j + 1], hi, part);
    }

    if (half == 1) sh_partial[wordlocal] = part;
    __syncthreads();

    double v = 0.0;
    if (half == 0) {
        const int n = base + wordlocal;
        if (n < N) {
            float covf = part + sh_partial[wordlocal];
            double cov = (double)covf * (double)p2a * (double)p2b;
            float c = coeff[n];
            v = (double)(c * c) / cov;
        }
        #pragma unroll
        for (int off = 16; off; off >>= 1)
            v += __shfl_down_sync(0xFFFFFFFFu, v, off);
        if (lane == 0) sh_red[wid >> 1] = v;
    }
    __syncthreads();
    if (tid == 0) {
        double s = 0.0;
        #pragma unroll
        for (int w = 0; w < 8; w++) s += sh_red[w];
        atomicAdd(&g_accum, s);
        __threadfence();
        unsigned int ticket = atomicAdd(&g_count, 1u);
        if (ticket == (unsigned int)(nblocks - 1)) {
            out[0] = (float)g_accum;
        }
    }
}

// ---------------------------------------------------------------------------
extern "C" void kernel_launch(void* const* d_in, const int* in_sizes, int n_in,
                              void* d_out, int out_size) {
    const float* pauli = (const float*)d_in[0];   // [N, 50, 3] f32
    const float* coeff = (const float*)d_in[1];   // [N] f32
    const float* heads = (const float*)d_in[2];   // [64, 50, 3] f32
    const float* hr    = (const float*)d_in[3];   // [64] f32
    const int N = in_sizes[1];

    const size_t smem = (size_t)(H_TOTAL + SS + WORDS + 16 + WORDS * TROW) * sizeof(float);
    cudaFuncSetAttribute(main_kernel, cudaFuncAttributeMaxDynamicSharedMemorySize, (int)smem);

    prep_kernel<<<25, 128>>>(heads, hr);
    const int grid = (N + WORDS - 1) / WORDS;
    main_kernel<<<grid, THREADS, smem>>>(pauli, coeff, (float*)d_out, N, grid);
}

// round 5
// speedup vs baseline: 1.3617x; 1.2447x over previous
#include <cuda_runtime.h>
#include <cstdint>

// Problem constants (shapes fixed by the dataset)
#define SQ 50          // qubits
#define SP 3           // pauli basis
#define SS 64          // heads
#define WORDS 256      // pauli words per block
#define THREADS 512    // 16 warps; warp quads split 64 heads, 2 words/thread
#define TROW 156       // padded row stride in floats (conflict-free for LDS.128)

// Packed heads: ha[q][j(32 pairs)][4] = {h0s0,h0s1,h1s0,h1s1}; hc[q][j][2] = {h2s0,h2s1}
#define HA_TOTAL (SQ * 128)   // 6400 floats
#define HC_TOTAL (SQ * 64)    // 3200 floats

__device__ double       g_accum;
__device__ unsigned int g_count;
__device__ float        g_ha[HA_TOTAL];
__device__ float        g_hc[HC_TOTAL];
__device__ float        g_hr[SS];

__device__ __forceinline__ float softplus20(float x) {
    float y = x * 20.0f;
    return fmaxf(y, 0.0f) + log1pf(expf(-fabsf(y)));
}

// ---------------------------------------------------------------------------
__global__ void prep_kernel(const float* __restrict__ heads_param,
                            const float* __restrict__ hr_param) {
    const int tid = threadIdx.x;

    if (blockIdx.x == 0 && tid == 0) { g_accum = 0.0; g_count = 0u; }

    __shared__ float s_hr[SS];
    if (tid < SS) s_hr[tid] = softplus20(hr_param[tid]);
    __syncthreads();
    if (blockIdx.x == 0 && tid < SS) {
        float s = 0.0f;
        #pragma unroll
        for (int i = 0; i < SS; i++) s += s_hr[i];
        s = fmaxf(s, 1e-12f);
        g_hr[tid] = (s_hr[tid] / s + 0.001f / (float)SS) / 1.001f;
    }

    const int stride = blockDim.x * gridDim.x;
    for (int i = blockIdx.x * blockDim.x + tid; i < SS * SQ; i += stride) {
        int s = i / SQ;
        int q = i - s * SQ;
        const float* hp = heads_param + (s * SQ + q) * SP;
        float h0 = softplus20(hp[0]);
        float h1 = softplus20(hp[1]);
        float h2 = softplus20(hp[2]);
        float inv = 1.0f / fmaxf(h0 + h1 + h2, 1e-12f);
        h0 *= inv; h1 *= inv; h2 *= inv;
        int j = s >> 1, o = s & 1;
        g_ha[q * 128 + j * 4 + 0 + o] = h0;
        g_ha[q * 128 + j * 4 + 2 + o] = h1;
        g_hc[q * 64  + j * 2 + o]     = h2;
    }
}

// ---------------------------------------------------------------------------
// Per-q step for 2 words x 8 head-pairs.
// dot = t2c * (h2 + h0*(t0/t2c) + h1*(t1/t2c)); all-nonneg inner sums.
// ---------------------------------------------------------------------------
__device__ __forceinline__ void proc_q2(
    int qi,
    float t0a, float t1a, float t2a,     // word A
    float t0b, float t1b, float t2b,     // word B
    const float* __restrict__ sh_ha_q0,  // sh_ha + quarter*32
    const float* __restrict__ sh_hc_q0,  // sh_hc + quarter*16
    uint64_t* __restrict__ accA, uint64_t* __restrict__ accB,
    float& pAa, float& pAb, float& pBa, float& pBb)
{
    float t2ca = fmaxf(t2a, 1e-12f);
    float t2cb = fmaxf(t2b, 1e-12f);
    float ra, rb;
    asm("rcp.approx.f32 %0, %1;" : "=f"(ra) : "f"(t2ca));
    asm("rcp.approx.f32 %0, %1;" : "=f"(rb) : "f"(t2cb));
    float r0a = t0a * ra, r1a = t1a * ra;
    float r0b = t0b * rb, r1b = t1b * rb;
    if (qi < SQ / 2) { pAa *= t2ca; pBa *= t2cb; }
    else             { pAb *= t2ca; pBb *= t2cb; }

    uint64_t R0A, R1A, R0B, R1B;
    asm("mov.b64 %0, {%1, %2};" : "=l"(R0A) : "f"(r0a), "f"(r0a));
    asm("mov.b64 %0, {%1, %2};" : "=l"(R1A) : "f"(r1a), "f"(r1a));
    asm("mov.b64 %0, {%1, %2};" : "=l"(R0B) : "f"(r0b), "f"(r0b));
    asm("mov.b64 %0, {%1, %2};" : "=l"(R1B) : "f"(r1b), "f"(r1b));

    const ulonglong2* ha = (const ulonglong2*)(sh_ha_q0 + qi * 128);
    const uint64_t*   hc = (const uint64_t*)  (sh_hc_q0 + qi * 64);
    #pragma unroll
    for (int j = 0; j < 8; j++) {
        ulonglong2 Ha = ha[j];     // {(h0 s0,s1), (h1 s0,s1)} 16B
        uint64_t   Hc = hc[j];     // (h2 s0,s1) 8B
        uint64_t dA, dB;
        asm("fma.rn.f32x2 %0, %1, %2, %3;" : "=l"(dA) : "l"(Ha.x), "l"(R0A), "l"(Hc));
        asm("fma.rn.f32x2 %0, %1, %2, %3;" : "=l"(dB) : "l"(Ha.x), "l"(R0B), "l"(Hc));
        asm("fma.rn.f32x2 %0, %1, %2, %3;" : "=l"(dA) : "l"(Ha.y), "l"(R1A), "l"(dA));
        asm("fma.rn.f32x2 %0, %1, %2, %3;" : "=l"(dB) : "l"(Ha.y), "l"(R1B), "l"(dB));
        asm("mul.rn.f32x2 %0, %1, %2;"     : "=l"(accA[j]) : "l"(accA[j]), "l"(dA));
        asm("mul.rn.f32x2 %0, %1, %2;"     : "=l"(accB[j]) : "l"(accB[j]), "l"(dB));
    }
}

// ---------------------------------------------------------------------------
// Main: warp quad g=wid>>2 covers words [g*64, g*64+64); quarter = wid&3
// handles head pairs quarter*8..quarter*8+7. Thread words: lane, lane+32.
// ---------------------------------------------------------------------------
__global__ void __launch_bounds__(THREADS, 1)
main_kernel(const float* __restrict__ pauli,
            const float* __restrict__ coeff,
            float* __restrict__ out,
            int N, int nblocks) {
    extern __shared__ float smem[];
    float*  sh_ha   = smem;                        // 6400
    float*  sh_hc   = smem + HA_TOTAL;             // 3200
    float*  sh_hr   = smem + HA_TOTAL + HC_TOTAL;  // 64   (offset 9600)
    float*  sh_part = smem + 9664;                 // 3*256 = 768
    double* sh_red  = (double*)(smem + 10432);     // 16 doubles (32 floats)
    float*  sh_t    = smem + 10464;                // 256*156 floats, 16B-aligned

    const int tid  = threadIdx.x;
    const int wid  = tid >> 5;
    const int lane = tid & 31;

    // Stage packed heads
    {
        const float4* src = (const float4*)g_ha;
        float4*       dst = (float4*)sh_ha;
        #pragma unroll
        for (int i = tid; i < HA_TOTAL / 4; i += THREADS) dst[i] = src[i];
        const float4* src2 = (const float4*)g_hc;
        float4*       dst2 = (float4*)sh_hc;
        #pragma unroll
        for (int i = tid; i < HC_TOTAL / 4; i += THREADS) dst2[i] = src2[i];
    }
    if (tid < SS) sh_hr[tid] = g_hr[tid];

    // Stage pauli tile: coalesced global reads, padded-row scatter
    const int base  = blockIdx.x * WORDS;
    const int valid = min(WORDS, N - base);
    const int total = valid * (SQ * SP);
    const float* gsrc = pauli + (size_t)base * (SQ * SP);
    for (int f = tid; f < total; f += THREADS) {
        int row = f / (SQ * SP);
        int col = f - row * (SQ * SP);
        sh_t[row * TROW + col] = gsrc[f];
    }
    __syncthreads();

    const int quarter = wid & 3;
    const int group   = wid >> 2;
    const int wA = group * 64 + lane;        // word A (local)
    const int wB = wA + 32;                  // word B (local)
    const float* trowA = sh_t + wA * TROW;
    const float* trowB = sh_t + wB * TROW;
    const float* sh_ha_q0 = sh_ha + quarter * 32;   // 8 pairs * 4 floats
    const float* sh_hc_q0 = sh_hc + quarter * 16;   // 8 pairs * 2 floats

    uint64_t accA[8], accB[8];
    #pragma unroll
    for (int j = 0; j < 8; j++) { accA[j] = 0x3F8000003F800000ull; accB[j] = accA[j]; }
    float pAa = 1.0f, pAb = 1.0f, pBa = 1.0f, pBb = 1.0f;

    const float4* tvA = (const float4*)trowA;
    const float4* tvB = (const float4*)trowB;
    #pragma unroll 4
    for (int c = 0; c < 12; c++) {
        float4 A0 = tvA[3 * c + 0], A1 = tvA[3 * c + 1], A2 = tvA[3 * c + 2];
        float4 B0 = tvB[3 * c + 0], B1 = tvB[3 * c + 1], B2 = tvB[3 * c + 2];
        proc_q2(4 * c + 0, A0.x, A0.y, A0.z, B0.x, B0.y, B0.z, sh_ha_q0, sh_hc_q0, accA, accB, pAa, pAb, pBa, pBb);
        proc_q2(4 * c + 1, A0.w, A1.x, A1.y, B0.w, B1.x, B1.y, sh_ha_q0, sh_hc_q0, accA, accB, pAa, pAb, pBa, pBb);
        proc_q2(4 * c + 2, A1.z, A1.w, A2.x, B1.z, B1.w, B2.x, sh_ha_q0, sh_hc_q0, accA, accB, pAa, pAb, pBa, pBb);
        proc_q2(4 * c + 3, A2.y, A2.z, A2.w, B2.y, B2.z, B2.w, sh_ha_q0, sh_hc_q0, accA, accB, pAa, pAb, pBa, pBb);
    }
    {   // q = 48, 49 (cols 144..149, 8B-aligned)
        const float2* a2 = (const float2*)(trowA + 144);
        const float2* b2 = (const float2*)(trowB + 144);
        float2 ua = a2[0], va = a2[1], wa = a2[2];
        float2 ub = b2[0], vb = b2[1], wb = b2[2];
        proc_q2(48, ua.x, ua.y, va.x, ub.x, ub.y, vb.x, sh_ha_q0, sh_hc_q0, accA, accB, pAa, pAb, pBa, pBb);
        proc_q2(49, va.y, wa.x, wa.y, vb.y, wb.x, wb.y, sh_ha_q0, sh_hc_q0, accA, accB, pAa, pAb, pBa, pBb);
    }

    // hr-weighted sums over this quarter's 16 heads
    float partA = 0.0f, partB = 0.0f;
    const float* hrq = sh_hr + quarter * 16;
    #pragma unroll
    for (int j = 0; j < 8; j++) {
        float lo, hi;
        asm("mov.b64 {%0, %1}, %2;" : "=f"(lo), "=f"(hi) : "l"(accA[j]));
        partA = fmaf(hrq[2 * j], lo, partA);
        partA = fmaf(hrq[2 * j + 1], hi, partA);
        asm("mov.b64 {%0, %1}, %2;" : "=f"(lo), "=f"(hi) : "l"(accB[j]));
        partB = fmaf(hrq[2 * j], lo, partB);
        partB = fmaf(hrq[2 * j + 1], hi, partB);
    }

    if (quarter != 0) {
        sh_part[(quarter - 1) * WORDS + wA] = partA;
        sh_part[(quarter - 1) * WORDS + wB] = partB;
    }
    __syncthreads();

    double v = 0.0;
    if (quarter == 0) {
        int nA = base + wA;
        if (nA < N) {
            float covf = partA + sh_part[wA] + sh_part[WORDS + wA] + sh_part[2 * WORDS + wA];
            double cov = (double)covf * (double)pAa * (double)pAb;
            float c = coeff[nA];
            v = (double)(c * c) / cov;
        }
        int nB = base + wB;
        if (nB < N) {
            float covf = partB + sh_part[wB] + sh_part[WORDS + wB] + sh_part[2 * WORDS + wB];
            double cov = (double)covf * (double)pBa * (double)pBb;
            float c = coeff[nB];
            v += (double)(c * c) / cov;
        }
        #pragma unroll
        for (int off = 16; off; off >>= 1)
            v += __shfl_down_sync(0xFFFFFFFFu, v, off);
        if (lane == 0) sh_red[group] = v;
    }
    __syncthreads();
    if (tid == 0) {
        double s = 0.0;
        #pragma unroll
        for (int w = 0; w < 4; w++) s += sh_red[w];
        atomicAdd(&g_accum, s);
        __threadfence();
        unsigned int ticket = atomicAdd(&g_count, 1u);
        if (ticket == (unsigned int)(nblocks - 1)) {
            out[0] = (float)g_accum;
        }
    }
}

// ---------------------------------------------------------------------------
extern "C" void kernel_launch(void* const* d_in, const int* in_sizes, int n_in,
                              void* d_out, int out_size) {
    const float* pauli = (const float*)d_in[0];   // [N, 50, 3] f32
    const float* coeff = (const float*)d_in[1];   // [N] f32
    const float* heads = (const float*)d_in[2];   // [64, 50, 3] f32
    const float* hr    = (const float*)d_in[3];   // [64] f32
    const int N = in_sizes[1];

    const size_t smem = (size_t)(10464 + WORDS * TROW) * sizeof(float);  // ~201.6 KB
    cudaFuncSetAttribute(main_kernel, cudaFuncAttributeMaxDynamicSharedMemorySize, (int)smem);

    prep_kernel<<<25, 128>>>(heads, hr);
    const int grid = (N + WORDS - 1) / WORDS;
    main_kernel<<<grid, THREADS, smem>>>(pauli, coeff, (float*)d_out, N, grid);
}